// round 15
// baseline (speedup 1.0000x reference)
#include <cuda_runtime.h>
#include <cuda_fp16.h>
#include <math.h>
#include <stdint.h>

#define Ldim 2048
#define Nb   4
#define E    768
#define H    12
#define HD   64
#define BH   (Nb*H)         /* 48 */
#define Mrows (Ldim*Nb)     /* 8192 */
#define EE   (E*E)          /* 589824 */
#define MK   (Mrows*E)      /* 6291456 */

// ---------------- scratch (static device globals; no runtime allocation) ----
__device__ float g_v[MK];
__device__ __half g_wh[4*EE];
__device__ __half g_xf[3*MK];
__device__ __half g_of[MK];
__device__ __half g_qf[BH*Ldim*HD];
__device__ __half g_kh[BH*Ldim*HD];
__device__ __half g_vth[BH*HD*Ldim];

// ============================ helpers ========================================
__device__ __forceinline__ uint32_t smem_u32(const void* p) {
    uint32_t a;
    asm("{ .reg .u64 t; cvta.to.shared.u64 t, %1; cvt.u32.u64 %0, t; }"
        : "=r"(a) : "l"(p));
    return a;
}
__device__ __forceinline__ float ex2f(float x) {
    float y; asm("ex2.approx.f32 %0, %1;" : "=f"(y) : "f"(x)); return y;
}
#define STS128(addr, r0, r1, r2, r3) \
    asm volatile("st.shared.v4.b32 [%0], {%1, %2, %3, %4};" \
                 :: "r"(addr), "r"(r0), "r"(r1), "r"(r2), "r"(r3) : "memory")

__device__ __forceinline__ void cpa16(uint32_t dst, const void* src) {
    asm volatile("cp.async.cg.shared.global [%0], [%1], 16;"
                 :: "r"(dst), "l"(src) : "memory");
}
#define CP_COMMIT() asm volatile("cp.async.commit_group;" ::: "memory")
#define CP_WAIT0()  asm volatile("cp.async.wait_group 0;" ::: "memory")

__device__ __forceinline__ void ldm_x4(uint32_t* r, uint32_t addr) {
    asm volatile("ldmatrix.sync.aligned.m8n8.x4.shared.b16 {%0,%1,%2,%3}, [%4];"
                 : "=r"(r[0]), "=r"(r[1]), "=r"(r[2]), "=r"(r[3]) : "r"(addr));
}
__device__ __forceinline__ void ldm_x2(uint32_t* r, uint32_t addr) {
    asm volatile("ldmatrix.sync.aligned.m8n8.x2.shared.b16 {%0,%1}, [%2];"
                 : "=r"(r[0]), "=r"(r[1]) : "r"(addr));
}
__device__ __forceinline__ void mma16816(float* c, const uint32_t* a,
                                         const uint32_t* b) {
    asm volatile(
        "mma.sync.aligned.m16n8k16.row.col.f32.f16.f16.f32 "
        "{%0,%1,%2,%3}, {%4,%5,%6,%7}, {%8,%9}, {%0,%1,%2,%3};"
        : "+f"(c[0]), "+f"(c[1]), "+f"(c[2]), "+f"(c[3])
        : "r"(a[0]), "r"(a[1]), "r"(a[2]), "r"(a[3]), "r"(b[0]), "r"(b[1]));
}
__device__ __forceinline__ uint32_t pack2h(float a, float b) {
    __half2 h = __floats2half2_rn(a, b);
    return *reinterpret_cast<uint32_t*>(&h);
}

// ---------------- combined: W_eff fp16 pack + x fp16 pack --------------------
#define WEFF_BLOCKS 4608            /* 4 * EE/2 / 256 */
#define XSPL_BLOCKS 18432           /* 3 * MK/4 / 256 */

__global__ void __launch_bounds__(256) weff_split_kernel(
    const float* __restrict__ inW,  const float* __restrict__ outW,
    const float* __restrict__ qd, const float* __restrict__ qu,
    const float* __restrict__ kd, const float* __restrict__ ku,
    const float* __restrict__ vd, const float* __restrict__ vu,
    const float* __restrict__ od, const float* __restrict__ ou,
    const float* __restrict__ query, const float* __restrict__ key,
    const float* __restrict__ value)
{
    int bx = blockIdx.x;
    if (bx < WEFF_BLOCKS) {
        int z = bx / (WEFF_BLOCKS / 4);
        int pidx = (bx % (WEFF_BLOCKS / 4)) * 256 + threadIdx.x;
        int e = (pidx * 2) / E;
        int k = (pidx * 2) % E;
        const float* W  = (z < 3) ? (inW + z * EE) : outW;
        const float* dn = (z == 0) ? qd : (z == 1) ? kd : (z == 2) ? vd : od;
        const float* up = (z == 0) ? qu : (z == 1) ? ku : (z == 2) ? vu : ou;
        float s0 = 0.f, s1 = 0.f;
#pragma unroll
        for (int r = 0; r < 16; r++) {
            float u = up[e * 16 + r];
            s0 += u * dn[r * E + k];
            s1 += u * dn[r * E + k + 1];
        }
        float v0 = W[e * E + k] + s0;
        float v1 = W[e * E + k + 1] + s1;
        ((uint32_t*)g_wh)[(size_t)z * (EE / 2) + pidx] = pack2h(v0, v1);
    } else {
        int i = bx - WEFF_BLOCKS;
        int z = i / (XSPL_BLOCKS / 3);
        size_t idx = (size_t)(i % (XSPL_BLOCKS / 3)) * 256 + threadIdx.x;
        const float4* src = (const float4*)((z == 0) ? query : (z == 1) ? key : value);
        float4 v = src[idx];
        ((uint2*)g_xf)[(size_t)z * (MK / 4) + idx] =
            make_uint2(pack2h(v.x, v.y), pack2h(v.z, v.w));
    }
}

// ================= fp16 single-pass MMA GEMM (K-chunk 64, 1 sync/iter) =======
#define SKG 144                /* smem row stride bytes (64 fp16 + 16 pad) */
#define GA_F 0
#define GB_H 18432
#define GSTG 36864
#define G_SMEM (2*GSTG)        /* 73728 */
#define GKT (E/64)             /* 12 k-stages */

__device__ __forceinline__ void g_prefetch(
    uint32_t buf, const __half* axf, const __half* bwh,
    int m0, int e0, int k0, int tid)
{
    int row = tid >> 1, part = tid & 1;
    uint32_t ro = (uint32_t)row * SKG + (uint32_t)part * 64;
    const __half* af = axf + (size_t)(m0 + row) * E + k0 + part * 32;
    const __half* bh = bwh + (size_t)(e0 + row) * E + k0 + part * 32;
#pragma unroll
    for (int c = 0; c < 4; c++) {
        cpa16(buf + GA_F + ro + c * 16, af + c * 8);
        cpa16(buf + GB_H + ro + c * 16, bh + c * 8);
    }
}

__global__ void __launch_bounds__(256, 2) gemm_mma(
    const __half* __restrict__ xf, const __half* __restrict__ wh,
    const float* __restrict__ bias_base,
    float* __restrict__ yout, int mode)
{
    extern __shared__ __align__(128) char smem[];
    uint32_t sb = smem_u32(smem);
    int z = blockIdx.z;
    const __half* axf = xf + (size_t)z * MK;
    const __half* bwh = wh + (size_t)z * EE;
    const float* bias = bias_base + z * E;
    int m0 = blockIdx.y * 128, e0 = blockIdx.x * 128;
    int tid = threadIdx.x, wid = tid >> 5, lane = tid & 31;
    int wm = wid & 1, wn = wid >> 1;

    uint32_t arow = (uint32_t)(wm * 64 + (lane & 15)) * SKG + (uint32_t)(lane >> 4) * 16;
    uint32_t brow = (uint32_t)(wn * 32 + (lane >> 4) * 8 + (lane & 7)) * SKG
                  + (uint32_t)((lane >> 3) & 1) * 16;

    float acc[4][4][4];
#pragma unroll
    for (int a = 0; a < 4; a++)
#pragma unroll
        for (int b = 0; b < 4; b++)
#pragma unroll
            for (int c = 0; c < 4; c++) acc[a][b][c] = 0.f;

    g_prefetch(sb, axf, bwh, m0, e0, 0, tid);
    CP_COMMIT();

    for (int kt = 0; kt < GKT; kt++) {
        uint32_t cb = sb + (uint32_t)(kt & 1) * GSTG;
        CP_WAIT0();
        __syncthreads();
        if (kt + 1 < GKT) {
            g_prefetch(sb + (uint32_t)((kt + 1) & 1) * GSTG,
                       axf, bwh, m0, e0, (kt + 1) * 64, tid);
            CP_COMMIT();
        }
#pragma unroll
        for (int ks = 0; ks < 4; ks++) {
            uint32_t koff = (uint32_t)ks * 32;
            uint32_t bhf[2][4];
            ldm_x4(bhf[0], cb + GB_H + brow + koff);
            ldm_x4(bhf[1], cb + GB_H + brow + 16 * SKG + koff);
#pragma unroll
            for (int mi = 0; mi < 4; mi++) {
                uint32_t af[4];
                ldm_x4(af, cb + GA_F + arow + mi * 16 * SKG + koff);
#pragma unroll
                for (int ni = 0; ni < 4; ni++)
                    mma16816(acc[mi][ni], af, bhf[ni >> 1] + (ni & 1) * 2);
            }
        }
    }

    int r = lane >> 2, cp = (lane & 3) * 2;
    if (mode == 1 && z < 2) {
        float qs = (z == 0) ? 0.125f * 1.4426950408889634f : 1.0f;
        __half* dst = (z == 0) ? g_qf : g_kh;
#pragma unroll
        for (int mi = 0; mi < 4; mi++) {
#pragma unroll
            for (int ni = 0; ni < 4; ni++) {
                int col = e0 + wn * 32 + ni * 8 + cp;
                int hh = col >> 6, d = col & 63;
                float b0 = bias[col], b1 = bias[col + 1];
#pragma unroll
                for (int rr = 0; rr < 2; rr++) {
                    int row = m0 + wm * 64 + mi * 16 + r + rr * 8;
                    int l = row >> 2, nb = row & 3;
                    size_t w = ((((size_t)(nb * H + hh) * Ldim + l) * HD) + d) >> 1;
                    float a = (acc[mi][ni][2 * rr]     + b0) * qs;
                    float b = (acc[mi][ni][2 * rr + 1] + b1) * qs;
                    ((uint32_t*)dst)[w] = pack2h(a, b);
                }
            }
        }
    } else {
        float* y = (mode == 1) ? g_v : yout;
#pragma unroll
        for (int mi = 0; mi < 4; mi++) {
            int row0 = m0 + wm * 64 + mi * 16 + r;
#pragma unroll
            for (int ni = 0; ni < 4; ni++) {
                int col = e0 + wn * 32 + ni * 8 + cp;
                float b0 = bias[col], b1 = bias[col + 1];
                float2 v0 = make_float2(acc[mi][ni][0] + b0, acc[mi][ni][1] + b1);
                float2 v1 = make_float2(acc[mi][ni][2] + b0, acc[mi][ni][3] + b1);
                *(float2*)(y + (size_t)row0 * E + col) = v0;
                *(float2*)(y + (size_t)(row0 + 8) * E + col) = v1;
            }
        }
    }
}

// ---------------- prep: v -> transposed fp16 [bh][d][L] ----------------------
__global__ void __launch_bounds__(256) v_prep()
{
    __shared__ float vt[64][65];
    int bh = blockIdx.y;
    int s0 = blockIdx.x * 64;
    int nb = bh / H, h = bh % H;
    int t = threadIdx.x;
    {
        int s = t >> 2, dq = (t & 3) * 16;
        const float* src = g_v + ((size_t)(s0 + s) * Nb + nb) * E + h * HD + dq;
#pragma unroll
        for (int j = 0; j < 4; j++) {
            float4 v = *(const float4*)(src + j * 4);
            vt[s][dq + j * 4 + 0] = v.x;
            vt[s][dq + j * 4 + 1] = v.y;
            vt[s][dq + j * 4 + 2] = v.z;
            vt[s][dq + j * 4 + 3] = v.w;
        }
    }
    __syncthreads();
    {
        int d = t >> 2, sq = (t & 3) * 16;
        uint32_t hw[8];
#pragma unroll
        for (int j = 0; j < 8; j++)
            hw[j] = pack2h(vt[sq + 2 * j][d], vt[sq + 2 * j + 1][d]);
        size_t dst = ((size_t)bh * HD + d) * Ldim + s0 + sq;
        ((uint4*)(g_vth + dst))[0] = make_uint4(hw[0], hw[1], hw[2], hw[3]);
        ((uint4*)(g_vth + dst))[1] = make_uint4(hw[4], hw[5], hw[6], hw[7]);
    }
}

// ================= warp-MMA flash attention ==================================
// K,V single fp16, 64-row stages; constant [ones;zeros] 8-row block in a
// separate smem area gives l via one extra n=8 MMA (fragment loaded once).
// Single __syncthreads per tile (wait -> sync -> prefetch -> compute).
#define SKB 144
#define STAGE_B 18432          /* KH 9216 + VH 9216 */
#define KH_O 0
#define VH_O 9216
#define VCONST (2*STAGE_B)     /* 8 x 144 const rows */
#define S_TOTAL3 (2*STAGE_B + 8*SKB)   /* 38016 */
#define NT (Ldim / 64)

__device__ __forceinline__ void kv_prefetch(uint32_t buf, int bh, int s0, int tid)
{
    int m = tid >> 1;
    int hf = tid & 1;
    uint32_t ro = (uint32_t)m * SKB + (uint32_t)hf * 64;
    const __half* kh = g_kh + ((size_t)bh * Ldim + s0 + m) * HD + hf * 32;
    const __half* vh = g_vth + ((size_t)bh * HD + m) * Ldim + s0 + hf * 32;
#pragma unroll
    for (int c = 0; c < 4; c++) {
        cpa16(buf + KH_O + ro + c * 16, kh + c * 8);
        cpa16(buf + VH_O + ro + c * 16, vh + c * 8);
    }
}

__global__ void __launch_bounds__(128, 4) attn_mma3()
{
    extern __shared__ __align__(128) char smem[];
    uint32_t sb = smem_u32(smem);
    int tid = threadIdx.x;
    int wid = tid >> 5, lane = tid & 31;
    int bh = blockIdx.y;
    int nb = bh / H, h = bh % H;
    int q0 = blockIdx.x * 64;

    kv_prefetch(sb, bh, 0, tid);
    CP_COMMIT();

    // init constant rows: row 0 = 1.0h, rows 1-7 = 0 (72 chunks of 16B)
    if (tid < 72) {
        int rr = tid / 9, ch = tid % 9;
        uint32_t a = sb + VCONST + (uint32_t)rr * SKB + (uint32_t)ch * 16;
        uint32_t v = (rr == 0) ? 0x3C003C00u : 0u;
        STS128(a, v, v, v, v);
    }

    // stage Q through stage-1 KH region (warp-local rows; consumed pre-loop)
    {
        uint32_t q_s = sb + STAGE_B + KH_O;
        int m = tid >> 1;
        int u0 = (tid & 1) * 4;
        uint32_t o = (uint32_t)m * SKB + (uint32_t)u0 * 16;
        const uint4* s = (const uint4*)(g_qf + ((size_t)bh * Ldim + q0 + m) * HD) + u0;
        uint4 a = s[0], b = s[1], c = s[2], d = s[3];
        STS128(q_s + o,      a.x, a.y, a.z, a.w);
        STS128(q_s + o + 16, b.x, b.y, b.z, b.w);
        STS128(q_s + o + 32, c.x, c.y, c.z, c.w);
        STS128(q_s + o + 48, d.x, d.y, d.z, d.w);
    }
    __syncthreads();

    uint32_t qrow = (uint32_t)(16 * wid + (lane & 15)) * SKB + (uint32_t)(lane >> 4) * 16;
    uint32_t brow = (uint32_t)(((lane >> 4) * 8 + (lane & 7))) * SKB
                  + (uint32_t)((lane >> 3) & 1) * 16;

    uint32_t qf[4][4];
#pragma unroll
    for (int k = 0; k < 4; k++)
        ldm_x4(qf[k], sb + STAGE_B + KH_O + qrow + k * 32);
    // constant ones-block B fragment (identical for every k-chunk)
    uint32_t ve[2];
    ldm_x2(ve, sb + VCONST + (uint32_t)(lane & 7) * SKB
               + (uint32_t)((lane >> 3) & 1) * 16);

    // Oa[0..7] = O columns; Oa[8] col 64 = l
    float Oa[9][4];
#pragma unroll
    for (int n = 0; n < 9; n++)
#pragma unroll
        for (int j = 0; j < 4; j++) Oa[n][j] = 0.f;
    float m_lo = -INFINITY, m_hi = -INFINITY;

    for (int t = 0; t < NT; t++) {
        uint32_t cb = sb + (uint32_t)(t & 1) * STAGE_B;
        CP_WAIT0();
        __syncthreads();
        if (t + 1 < NT) {
            kv_prefetch(sb + (uint32_t)((t + 1) & 1) * STAGE_B,
                        bh, (t + 1) * 64, tid);
            CP_COMMIT();
        }

        // ---- S = Q K^T -------------------------------------------------------
        float c[8][4];
#pragma unroll
        for (int n = 0; n < 8; n++)
#pragma unroll
            for (int j = 0; j < 4; j++) c[n][j] = 0.f;
#pragma unroll
        for (int np = 0; np < 4; np++) {
            uint32_t baseH = cb + KH_O + brow + np * (16 * SKB);
#pragma unroll
            for (int k = 0; k < 4; k++) {
                uint32_t bhh[4];
                ldm_x4(bhh, baseH + k * 32);
                mma16816(c[2 * np],     qf[k], bhh);
                mma16816(c[2 * np + 1], qf[k], bhh + 2);
            }
        }

        // ---- online softmax (quad-local rows) -------------------------------
        float mn_lo = m_lo, mn_hi = m_hi;
#pragma unroll
        for (int n = 0; n < 8; n++) {
            mn_lo = fmaxf(mn_lo, fmaxf(c[n][0], c[n][1]));
            mn_hi = fmaxf(mn_hi, fmaxf(c[n][2], c[n][3]));
        }
        mn_lo = fmaxf(mn_lo, __shfl_xor_sync(0xffffffffu, mn_lo, 1));
        mn_lo = fmaxf(mn_lo, __shfl_xor_sync(0xffffffffu, mn_lo, 2));
        mn_hi = fmaxf(mn_hi, __shfl_xor_sync(0xffffffffu, mn_hi, 1));
        mn_hi = fmaxf(mn_hi, __shfl_xor_sync(0xffffffffu, mn_hi, 2));
        bool upd = (mn_lo > m_lo) || (mn_hi > m_hi);
        if (__any_sync(0xffffffffu, upd)) {
            float corr_lo = ex2f(m_lo - mn_lo);
            float corr_hi = ex2f(m_hi - mn_hi);
#pragma unroll
            for (int n = 0; n < 9; n++) {
                Oa[n][0] *= corr_lo; Oa[n][1] *= corr_lo;
                Oa[n][2] *= corr_hi; Oa[n][3] *= corr_hi;
            }
        }
        m_lo = mn_lo; m_hi = mn_hi;

        uint32_t ph[4][4];
#pragma unroll
        for (int n = 0; n < 8; n++) {
            float p0 = ex2f(c[n][0] - m_lo);
            float p1 = ex2f(c[n][1] - m_lo);
            float p2 = ex2f(c[n][2] - m_hi);
            float p3 = ex2f(c[n][3] - m_hi);
            int kc = n >> 1, o = (n & 1) * 2;
            ph[kc][o]     = pack2h(p0, p1);
            ph[kc][o + 1] = pack2h(p2, p3);
        }

        // ---- O += P V ; l += P 1 ---------------------------------------------
#pragma unroll
        for (int np = 0; np < 4; np++) {
            uint32_t baseH = cb + VH_O + brow + np * (16 * SKB);
#pragma unroll
            for (int k = 0; k < 4; k++) {
                uint32_t vhh[4];
                ldm_x4(vhh, baseH + k * 32);
                mma16816(Oa[2 * np],     ph[k], vhh);
                mma16816(Oa[2 * np + 1], ph[k], vhh + 2);
            }
        }
#pragma unroll
        for (int k = 0; k < 4; k++)
            mma16816(Oa[8], ph[k], ve);
    }

    // ---- epilogue: broadcast l from quad-lane 0, normalize, fp16 pack --------
    float l_lo = __shfl_sync(0xffffffffu, Oa[8][0], lane & ~3);
    float l_hi = __shfl_sync(0xffffffffu, Oa[8][2], lane & ~3);
    float inv_lo = 1.f / l_lo, inv_hi = 1.f / l_hi;

    int r = lane >> 2, cc = (lane & 3) * 2;
    size_t base_lo = ((size_t)(q0 + 16 * wid + r) * Nb + nb) * E + h * HD;
    size_t base_hi = ((size_t)(q0 + 16 * wid + r + 8) * Nb + nb) * E + h * HD;
#pragma unroll
    for (int n = 0; n < 8; n++) {
        int d = n * 8 + cc;
        ((uint32_t*)g_of)[(base_lo + d) >> 1] =
            pack2h(Oa[n][0] * inv_lo, Oa[n][1] * inv_lo);
        ((uint32_t*)g_of)[(base_hi + d) >> 1] =
            pack2h(Oa[n][2] * inv_hi, Oa[n][3] * inv_hi);
    }
}

// ---------------- launcher ---------------------------------------------------
extern "C" void kernel_launch(void* const* d_in, const int* in_sizes, int n_in,
                              void* d_out, int out_size)
{
    const float* query = (const float*)d_in[0];
    const float* key   = (const float*)d_in[1];
    const float* value = (const float*)d_in[2];
    const float* in_w  = (const float*)d_in[3];
    const float* in_b  = (const float*)d_in[4];
    const float* q_dn  = (const float*)d_in[5];
    const float* q_up  = (const float*)d_in[6];
    const float* k_dn  = (const float*)d_in[7];
    const float* k_up  = (const float*)d_in[8];
    const float* v_dn  = (const float*)d_in[9];
    const float* v_up  = (const float*)d_in[10];
    const float* out_w = (const float*)d_in[11];
    const float* out_b = (const float*)d_in[12];
    const float* o_dn  = (const float*)d_in[13];
    const float* o_up  = (const float*)d_in[14];

    __half *p_wh, *p_xf, *p_of;
    cudaGetSymbolAddress((void**)&p_wh, g_wh);
    cudaGetSymbolAddress((void**)&p_xf, g_xf);
    cudaGetSymbolAddress((void**)&p_of, g_of);

    cudaFuncSetAttribute(attn_mma3,
                         cudaFuncAttributeMaxDynamicSharedMemorySize, S_TOTAL3);
    cudaFuncSetAttribute(gemm_mma,
                         cudaFuncAttributeMaxDynamicSharedMemorySize, G_SMEM);

    // 1) W_eff -> fp16 + input fp16 pack
    weff_split_kernel<<<WEFF_BLOCKS + XSPL_BLOCKS, 256>>>(
        in_w, out_w, q_dn, q_up, k_dn, k_up, v_dn, v_up, o_dn, o_up,
        query, key, value);
    // 2) QKV projections; q/k written in attention fp16 layout
    gemm_mma<<<dim3(E / 128, Mrows / 128, 3), 256, G_SMEM>>>(
        p_xf, p_wh, in_b, nullptr, /*mode=*/1);
    // 3) v transpose to fp16 [bh][d][L]
    v_prep<<<dim3(Ldim / 64, BH), 256>>>();
    // 4) warp-MMA flash attention (launch #4 -> profiled); writes g_of
    attn_mma3<<<dim3(Ldim / 64, BH), 128, S_TOTAL3>>>();
    // 5) output projection -> d_out (fp32)
    gemm_mma<<<dim3(E / 128, Mrows / 128, 1), 256, G_SMEM>>>(
        p_of, p_wh + 3 * (size_t)EE, out_b, (float*)d_out, /*mode=*/0);
}

// round 16
// speedup vs baseline: 1.0394x; 1.0394x over previous
#include <cuda_runtime.h>
#include <cuda_fp16.h>
#include <math.h>
#include <stdint.h>

#define Ldim 2048
#define Nb   4
#define E    768
#define H    12
#define HD   64
#define BH   (Nb*H)         /* 48 */
#define Mrows (Ldim*Nb)     /* 8192 */
#define EE   (E*E)          /* 589824 */
#define MK   (Mrows*E)      /* 6291456 */

// ---------------- scratch (static device globals; no runtime allocation) ----
__device__ __half g_wh[4*EE];
__device__ __half g_xf[3*MK];
__device__ __half g_of[MK];
__device__ __half g_qf[BH*Ldim*HD];
__device__ __half g_kh[BH*Ldim*HD];
__device__ __half g_vf[BH*Ldim*HD];     // V in [bh][l][64] fp16 (gemm epilogue)
__device__ __half g_vth[BH*HD*Ldim];    // V transposed [bh][d][L]

// ============================ helpers ========================================
__device__ __forceinline__ uint32_t smem_u32(const void* p) {
    uint32_t a;
    asm("{ .reg .u64 t; cvta.to.shared.u64 t, %1; cvt.u32.u64 %0, t; }"
        : "=r"(a) : "l"(p));
    return a;
}
__device__ __forceinline__ float ex2f(float x) {
    float y; asm("ex2.approx.f32 %0, %1;" : "=f"(y) : "f"(x)); return y;
}
#define STS128(addr, r0, r1, r2, r3) \
    asm volatile("st.shared.v4.b32 [%0], {%1, %2, %3, %4};" \
                 :: "r"(addr), "r"(r0), "r"(r1), "r"(r2), "r"(r3) : "memory")

__device__ __forceinline__ void cpa16(uint32_t dst, const void* src) {
    asm volatile("cp.async.cg.shared.global [%0], [%1], 16;"
                 :: "r"(dst), "l"(src) : "memory");
}
#define CP_COMMIT() asm volatile("cp.async.commit_group;" ::: "memory")
#define CP_WAIT1()  asm volatile("cp.async.wait_group 1;" ::: "memory")
#define CP_WAIT0()  asm volatile("cp.async.wait_group 0;" ::: "memory")

__device__ __forceinline__ void ldm_x4(uint32_t* r, uint32_t addr) {
    asm volatile("ldmatrix.sync.aligned.m8n8.x4.shared.b16 {%0,%1,%2,%3}, [%4];"
                 : "=r"(r[0]), "=r"(r[1]), "=r"(r[2]), "=r"(r[3]) : "r"(addr));
}
__device__ __forceinline__ void ldm_x2(uint32_t* r, uint32_t addr) {
    asm volatile("ldmatrix.sync.aligned.m8n8.x2.shared.b16 {%0,%1}, [%2];"
                 : "=r"(r[0]), "=r"(r[1]) : "r"(addr));
}
__device__ __forceinline__ void mma16816(float* c, const uint32_t* a,
                                         const uint32_t* b) {
    asm volatile(
        "mma.sync.aligned.m16n8k16.row.col.f32.f16.f16.f32 "
        "{%0,%1,%2,%3}, {%4,%5,%6,%7}, {%8,%9}, {%0,%1,%2,%3};"
        : "+f"(c[0]), "+f"(c[1]), "+f"(c[2]), "+f"(c[3])
        : "r"(a[0]), "r"(a[1]), "r"(a[2]), "r"(a[3]), "r"(b[0]), "r"(b[1]));
}
__device__ __forceinline__ uint32_t pack2h(float a, float b) {
    __half2 h = __floats2half2_rn(a, b);
    return *reinterpret_cast<uint32_t*>(&h);
}

// ---------------- combined: W_eff fp16 pack + x fp16 pack --------------------
#define WEFF_BLOCKS 4608            /* 4 * EE/2 / 256 */
#define XSPL_BLOCKS 18432           /* 3 * MK/4 / 256 */

__global__ void __launch_bounds__(256) weff_split_kernel(
    const float* __restrict__ inW,  const float* __restrict__ outW,
    const float* __restrict__ qd, const float* __restrict__ qu,
    const float* __restrict__ kd, const float* __restrict__ ku,
    const float* __restrict__ vd, const float* __restrict__ vu,
    const float* __restrict__ od, const float* __restrict__ ou,
    const float* __restrict__ query, const float* __restrict__ key,
    const float* __restrict__ value)
{
    int bx = blockIdx.x;
    if (bx < WEFF_BLOCKS) {
        int z = bx / (WEFF_BLOCKS / 4);
        int pidx = (bx % (WEFF_BLOCKS / 4)) * 256 + threadIdx.x;
        int e = (pidx * 2) / E;
        int k = (pidx * 2) % E;
        const float* W  = (z < 3) ? (inW + z * EE) : outW;
        const float* dn = (z == 0) ? qd : (z == 1) ? kd : (z == 2) ? vd : od;
        const float* up = (z == 0) ? qu : (z == 1) ? ku : (z == 2) ? vu : ou;
        float s0 = 0.f, s1 = 0.f;
#pragma unroll
        for (int r = 0; r < 16; r++) {
            float u = up[e * 16 + r];
            s0 += u * dn[r * E + k];
            s1 += u * dn[r * E + k + 1];
        }
        float v0 = W[e * E + k] + s0;
        float v1 = W[e * E + k + 1] + s1;
        ((uint32_t*)g_wh)[(size_t)z * (EE / 2) + pidx] = pack2h(v0, v1);
    } else {
        int i = bx - WEFF_BLOCKS;
        int z = i / (XSPL_BLOCKS / 3);
        size_t idx = (size_t)(i % (XSPL_BLOCKS / 3)) * 256 + threadIdx.x;
        const float4* src = (const float4*)((z == 0) ? query : (z == 1) ? key : value);
        float4 v = src[idx];
        ((uint2*)g_xf)[(size_t)z * (MK / 4) + idx] =
            make_uint2(pack2h(v.x, v.y), pack2h(v.z, v.w));
    }
}

// ================= fp16 single-pass MMA GEMM (R14 proven config) =============
// mode 0: write fp32 yout.  mode 1 (QKV): all z -> fp16 [bh][l][64]
// (z=0 g_qf scaled, z=1 g_kh, z=2 g_vf).
#define SKG 80                 /* smem row stride bytes (32 fp16 + pad) */
#define GA_F 0
#define GB_H 10240
#define GSTG 20480
#define G_SMEM (2*GSTG)        /* 40960 */
#define GKT (E/32)             /* 24 k-stages */

__device__ __forceinline__ void g_prefetch(
    uint32_t buf, const __half* axf, const __half* bwh,
    int m0, int e0, int k0, int tid)
{
    int row = tid >> 1, part = tid & 1;
    uint32_t ro = (uint32_t)row * SKG + (uint32_t)part * 32;
    const __half* af = axf + (size_t)(m0 + row) * E + k0 + part * 16;
    const __half* bh = bwh + (size_t)(e0 + row) * E + k0 + part * 16;
    cpa16(buf + GA_F + ro,      af); cpa16(buf + GA_F + ro + 16, af + 8);
    cpa16(buf + GB_H + ro,      bh); cpa16(buf + GB_H + ro + 16, bh + 8);
}

__global__ void __launch_bounds__(256, 2) gemm_mma(
    const __half* __restrict__ xf, const __half* __restrict__ wh,
    const float* __restrict__ bias_base,
    float* __restrict__ yout, int mode)
{
    extern __shared__ __align__(128) char smem[];
    uint32_t sb = smem_u32(smem);
    int z = blockIdx.z;
    const __half* axf = xf + (size_t)z * MK;
    const __half* bwh = wh + (size_t)z * EE;
    const float* bias = bias_base + z * E;
    int m0 = blockIdx.y * 128, e0 = blockIdx.x * 128;
    int tid = threadIdx.x, wid = tid >> 5, lane = tid & 31;
    int wm = wid & 1, wn = wid >> 1;

    uint32_t arow = (uint32_t)(wm * 64 + (lane & 15)) * SKG + (uint32_t)(lane >> 4) * 16;
    uint32_t brow = (uint32_t)(wn * 32 + (lane >> 4) * 8 + (lane & 7)) * SKG
                  + (uint32_t)((lane >> 3) & 1) * 16;

    float acc[4][4][4];
#pragma unroll
    for (int a = 0; a < 4; a++)
#pragma unroll
        for (int b = 0; b < 4; b++)
#pragma unroll
            for (int c = 0; c < 4; c++) acc[a][b][c] = 0.f;

    g_prefetch(sb, axf, bwh, m0, e0, 0, tid);
    CP_COMMIT();

    for (int kt = 0; kt < GKT; kt++) {
        uint32_t cb = sb + (uint32_t)(kt & 1) * GSTG;
        if (kt + 1 < GKT) {
            g_prefetch(sb + (uint32_t)((kt + 1) & 1) * GSTG,
                       axf, bwh, m0, e0, (kt + 1) * 32, tid);
            CP_COMMIT();
            CP_WAIT1();
        } else {
            CP_WAIT0();
        }
        __syncthreads();
#pragma unroll
        for (int ks = 0; ks < 2; ks++) {
            uint32_t koff = (uint32_t)ks * 32;
            uint32_t bhf[2][4];
            ldm_x4(bhf[0], cb + GB_H + brow + koff);
            ldm_x4(bhf[1], cb + GB_H + brow + 16 * SKG + koff);
#pragma unroll
            for (int mi = 0; mi < 4; mi++) {
                uint32_t af[4];
                ldm_x4(af, cb + GA_F + arow + mi * 16 * SKG + koff);
#pragma unroll
                for (int ni = 0; ni < 4; ni++)
                    mma16816(acc[mi][ni], af, bhf[ni >> 1] + (ni & 1) * 2);
            }
        }
        __syncthreads();
    }

    int r = lane >> 2, cp = (lane & 3) * 2;
    if (mode == 1) {
        float qs = (z == 0) ? 0.125f * 1.4426950408889634f : 1.0f;
        __half* dst = (z == 0) ? g_qf : (z == 1) ? g_kh : g_vf;
#pragma unroll
        for (int mi = 0; mi < 4; mi++) {
#pragma unroll
            for (int ni = 0; ni < 4; ni++) {
                int col = e0 + wn * 32 + ni * 8 + cp;
                int hh = col >> 6, d = col & 63;
                float b0 = bias[col], b1 = bias[col + 1];
#pragma unroll
                for (int rr = 0; rr < 2; rr++) {
                    int row = m0 + wm * 64 + mi * 16 + r + rr * 8;
                    int l = row >> 2, nb = row & 3;
                    size_t w = ((((size_t)(nb * H + hh) * Ldim + l) * HD) + d) >> 1;
                    float a = (acc[mi][ni][2 * rr]     + b0) * qs;
                    float b = (acc[mi][ni][2 * rr + 1] + b1) * qs;
                    ((uint32_t*)dst)[w] = pack2h(a, b);
                }
            }
        }
    } else {
#pragma unroll
        for (int mi = 0; mi < 4; mi++) {
            int row0 = m0 + wm * 64 + mi * 16 + r;
#pragma unroll
            for (int ni = 0; ni < 4; ni++) {
                int col = e0 + wn * 32 + ni * 8 + cp;
                float b0 = bias[col], b1 = bias[col + 1];
                float2 v0 = make_float2(acc[mi][ni][0] + b0, acc[mi][ni][1] + b1);
                float2 v1 = make_float2(acc[mi][ni][2] + b0, acc[mi][ni][3] + b1);
                *(float2*)(yout + (size_t)row0 * E + col) = v0;
                *(float2*)(yout + (size_t)(row0 + 8) * E + col) = v1;
            }
        }
    }
}

// ---------------- prep: fp16 transpose v [bh][l][64] -> [bh][d][L] -----------
__global__ void __launch_bounds__(256) v_prep()
{
    __shared__ __half vt[64][72];
    int bh = blockIdx.y;
    int s0 = blockIdx.x * 64;
    int t = threadIdx.x;
    {
        int s = t >> 2, dq = (t & 3) * 16;
        const uint4* src = (const uint4*)(g_vf + ((size_t)bh * Ldim + s0 + s) * HD + dq);
        uint4 a = src[0], b = src[1];
        *(uint4*)&vt[s][dq]     = a;
        *(uint4*)&vt[s][dq + 8] = b;
    }
    __syncthreads();
    {
        int d = t >> 2, sq = (t & 3) * 16;
        uint32_t hw[8];
#pragma unroll
        for (int j = 0; j < 8; j++) {
            uint32_t lo = *(const uint16_t*)&vt[sq + 2 * j][d];
            uint32_t hi = *(const uint16_t*)&vt[sq + 2 * j + 1][d];
            hw[j] = lo | (hi << 16);
        }
        size_t dst = ((size_t)bh * HD + d) * Ldim + s0 + sq;
        ((uint4*)(g_vth + dst))[0] = make_uint4(hw[0], hw[1], hw[2], hw[3]);
        ((uint4*)(g_vth + dst))[1] = make_uint4(hw[4], hw[5], hw[6], hw[7]);
    }
}

// ================= warp-MMA flash attention (R15 proven config) ==============
#define SKB 144
#define STAGE_B 18432          /* KH 9216 + VH 9216 */
#define KH_O 0
#define VH_O 9216
#define VCONST (2*STAGE_B)     /* 8 x 144 const rows */
#define S_TOTAL3 (2*STAGE_B + 8*SKB)   /* 38016 */
#define NT (Ldim / 64)

__device__ __forceinline__ void kv_prefetch(uint32_t buf, int bh, int s0, int tid)
{
    int m = tid >> 1;
    int hf = tid & 1;
    uint32_t ro = (uint32_t)m * SKB + (uint32_t)hf * 64;
    const __half* kh = g_kh + ((size_t)bh * Ldim + s0 + m) * HD + hf * 32;
    const __half* vh = g_vth + ((size_t)bh * HD + m) * Ldim + s0 + hf * 32;
#pragma unroll
    for (int c = 0; c < 4; c++) {
        cpa16(buf + KH_O + ro + c * 16, kh + c * 8);
        cpa16(buf + VH_O + ro + c * 16, vh + c * 8);
    }
}

__global__ void __launch_bounds__(128, 4) attn_mma3()
{
    extern __shared__ __align__(128) char smem[];
    uint32_t sb = smem_u32(smem);
    int tid = threadIdx.x;
    int wid = tid >> 5, lane = tid & 31;
    int bh = blockIdx.y;
    int nb = bh / H, h = bh % H;
    int q0 = blockIdx.x * 64;

    kv_prefetch(sb, bh, 0, tid);
    CP_COMMIT();

    // init constant rows: row 0 = 1.0h, rows 1-7 = 0 (72 chunks of 16B)
    if (tid < 72) {
        int rr = tid / 9, ch = tid % 9;
        uint32_t a = sb + VCONST + (uint32_t)rr * SKB + (uint32_t)ch * 16;
        uint32_t v = (rr == 0) ? 0x3C003C00u : 0u;
        STS128(a, v, v, v, v);
    }

    // stage Q through stage-1 KH region (transient; consumed pre-loop)
    {
        uint32_t q_s = sb + STAGE_B + KH_O;
        int m = tid >> 1;
        int u0 = (tid & 1) * 4;
        uint32_t o = (uint32_t)m * SKB + (uint32_t)u0 * 16;
        const uint4* s = (const uint4*)(g_qf + ((size_t)bh * Ldim + q0 + m) * HD) + u0;
        uint4 a = s[0], b = s[1], c = s[2], d = s[3];
        STS128(q_s + o,      a.x, a.y, a.z, a.w);
        STS128(q_s + o + 16, b.x, b.y, b.z, b.w);
        STS128(q_s + o + 32, c.x, c.y, c.z, c.w);
        STS128(q_s + o + 48, d.x, d.y, d.z, d.w);
    }
    __syncthreads();

    uint32_t qrow = (uint32_t)(16 * wid + (lane & 15)) * SKB + (uint32_t)(lane >> 4) * 16;
    uint32_t brow = (uint32_t)(((lane >> 4) * 8 + (lane & 7))) * SKB
                  + (uint32_t)((lane >> 3) & 1) * 16;

    uint32_t qf[4][4];
#pragma unroll
    for (int k = 0; k < 4; k++)
        ldm_x4(qf[k], sb + STAGE_B + KH_O + qrow + k * 32);
    // constant ones-block B fragment (identical for every k-chunk)
    uint32_t ve[2];
    ldm_x2(ve, sb + VCONST + (uint32_t)(lane & 7) * SKB
               + (uint32_t)((lane >> 3) & 1) * 16);

    // Oa[0..7] = O columns; Oa[8] col 64 = l
    float Oa[9][4];
#pragma unroll
    for (int n = 0; n < 9; n++)
#pragma unroll
        for (int j = 0; j < 4; j++) Oa[n][j] = 0.f;
    float m_lo = -INFINITY, m_hi = -INFINITY;

    for (int t = 0; t < NT; t++) {
        uint32_t cb = sb + (uint32_t)(t & 1) * STAGE_B;
        CP_WAIT0();
        __syncthreads();
        if (t + 1 < NT) {
            kv_prefetch(sb + (uint32_t)((t + 1) & 1) * STAGE_B,
                        bh, (t + 1) * 64, tid);
            CP_COMMIT();
        }

        // ---- S = Q K^T -------------------------------------------------------
        float c[8][4];
#pragma unroll
        for (int n = 0; n < 8; n++)
#pragma unroll
            for (int j = 0; j < 4; j++) c[n][j] = 0.f;
#pragma unroll
        for (int np = 0; np < 4; np++) {
            uint32_t baseH = cb + KH_O + brow + np * (16 * SKB);
#pragma unroll
            for (int k = 0; k < 4; k++) {
                uint32_t bhh[4];
                ldm_x4(bhh, baseH + k * 32);
                mma16816(c[2 * np],     qf[k], bhh);
                mma16816(c[2 * np + 1], qf[k], bhh + 2);
            }
        }

        // ---- online softmax (quad-local rows) -------------------------------
        float mn_lo = m_lo, mn_hi = m_hi;
#pragma unroll
        for (int n = 0; n < 8; n++) {
            mn_lo = fmaxf(mn_lo, fmaxf(c[n][0], c[n][1]));
            mn_hi = fmaxf(mn_hi, fmaxf(c[n][2], c[n][3]));
        }
        mn_lo = fmaxf(mn_lo, __shfl_xor_sync(0xffffffffu, mn_lo, 1));
        mn_lo = fmaxf(mn_lo, __shfl_xor_sync(0xffffffffu, mn_lo, 2));
        mn_hi = fmaxf(mn_hi, __shfl_xor_sync(0xffffffffu, mn_hi, 1));
        mn_hi = fmaxf(mn_hi, __shfl_xor_sync(0xffffffffu, mn_hi, 2));
        bool upd = (mn_lo > m_lo) || (mn_hi > m_hi);
        if (__any_sync(0xffffffffu, upd)) {
            float corr_lo = ex2f(m_lo - mn_lo);
            float corr_hi = ex2f(m_hi - mn_hi);
#pragma unroll
            for (int n = 0; n < 9; n++) {
                Oa[n][0] *= corr_lo; Oa[n][1] *= corr_lo;
                Oa[n][2] *= corr_hi; Oa[n][3] *= corr_hi;
            }
        }
        m_lo = mn_lo; m_hi = mn_hi;

        uint32_t ph[4][4];
#pragma unroll
        for (int n = 0; n < 8; n++) {
            float p0 = ex2f(c[n][0] - m_lo);
            float p1 = ex2f(c[n][1] - m_lo);
            float p2 = ex2f(c[n][2] - m_hi);
            float p3 = ex2f(c[n][3] - m_hi);
            int kc = n >> 1, o = (n & 1) * 2;
            ph[kc][o]     = pack2h(p0, p1);
            ph[kc][o + 1] = pack2h(p2, p3);
        }

        // ---- O += P V ; l += P 1 ---------------------------------------------
#pragma unroll
        for (int np = 0; np < 4; np++) {
            uint32_t baseH = cb + VH_O + brow + np * (16 * SKB);
#pragma unroll
            for (int k = 0; k < 4; k++) {
                uint32_t vhh[4];
                ldm_x4(vhh, baseH + k * 32);
                mma16816(Oa[2 * np],     ph[k], vhh);
                mma16816(Oa[2 * np + 1], ph[k], vhh + 2);
            }
        }
#pragma unroll
        for (int k = 0; k < 4; k++)
            mma16816(Oa[8], ph[k], ve);
    }

    // ---- epilogue: broadcast l from quad-lane 0, normalize, fp16 pack --------
    float l_lo = __shfl_sync(0xffffffffu, Oa[8][0], lane & ~3);
    float l_hi = __shfl_sync(0xffffffffu, Oa[8][2], lane & ~3);
    float inv_lo = 1.f / l_lo, inv_hi = 1.f / l_hi;

    int r = lane >> 2, cc = (lane & 3) * 2;
    size_t base_lo = ((size_t)(q0 + 16 * wid + r) * Nb + nb) * E + h * HD;
    size_t base_hi = ((size_t)(q0 + 16 * wid + r + 8) * Nb + nb) * E + h * HD;
#pragma unroll
    for (int n = 0; n < 8; n++) {
        int d = n * 8 + cc;
        ((uint32_t*)g_of)[(base_lo + d) >> 1] =
            pack2h(Oa[n][0] * inv_lo, Oa[n][1] * inv_lo);
        ((uint32_t*)g_of)[(base_hi + d) >> 1] =
            pack2h(Oa[n][2] * inv_hi, Oa[n][3] * inv_hi);
    }
}

// ---------------- launcher ---------------------------------------------------
extern "C" void kernel_launch(void* const* d_in, const int* in_sizes, int n_in,
                              void* d_out, int out_size)
{
    const float* query = (const float*)d_in[0];
    const float* key   = (const float*)d_in[1];
    const float* value = (const float*)d_in[2];
    const float* in_w  = (const float*)d_in[3];
    const float* in_b  = (const float*)d_in[4];
    const float* q_dn  = (const float*)d_in[5];
    const float* q_up  = (const float*)d_in[6];
    const float* k_dn  = (const float*)d_in[7];
    const float* k_up  = (const float*)d_in[8];
    const float* v_dn  = (const float*)d_in[9];
    const float* v_up  = (const float*)d_in[10];
    const float* out_w = (const float*)d_in[11];
    const float* out_b = (const float*)d_in[12];
    const float* o_dn  = (const float*)d_in[13];
    const float* o_up  = (const float*)d_in[14];

    __half *p_wh, *p_xf, *p_of;
    cudaGetSymbolAddress((void**)&p_wh, g_wh);
    cudaGetSymbolAddress((void**)&p_xf, g_xf);
    cudaGetSymbolAddress((void**)&p_of, g_of);

    cudaFuncSetAttribute(attn_mma3,
                         cudaFuncAttributeMaxDynamicSharedMemorySize, S_TOTAL3);
    cudaFuncSetAttribute(gemm_mma,
                         cudaFuncAttributeMaxDynamicSharedMemorySize, G_SMEM);

    // 1) W_eff -> fp16 + input fp16 pack
    weff_split_kernel<<<WEFF_BLOCKS + XSPL_BLOCKS, 256>>>(
        in_w, out_w, q_dn, q_up, k_dn, k_up, v_dn, v_up, o_dn, o_up,
        query, key, value);
    // 2) QKV projections; q/k/v all written in attention fp16 layout
    gemm_mma<<<dim3(E / 128, Mrows / 128, 3), 256, G_SMEM>>>(
        p_xf, p_wh, in_b, nullptr, /*mode=*/1);
    // 3) fp16 transpose v -> [bh][d][L]
    v_prep<<<dim3(Ldim / 64, BH), 256>>>();
    // 4) warp-MMA flash attention (launch #4 -> profiled); writes g_of
    attn_mma3<<<dim3(Ldim / 64, BH), 128, S_TOTAL3>>>();
    // 5) output projection -> d_out (fp32)
    gemm_mma<<<dim3(E / 128, Mrows / 128, 1), 256, G_SMEM>>>(
        p_of, p_wh + 3 * (size_t)EE, out_b, (float*)d_out, /*mode=*/0);
}

// round 17
// speedup vs baseline: 1.1023x; 1.0605x over previous
#include <cuda_runtime.h>
#include <cuda_fp16.h>
#include <math.h>
#include <stdint.h>

#define Ldim 2048
#define Nb   4
#define E    768
#define H    12
#define HD   64
#define BH   (Nb*H)         /* 48 */
#define Mrows (Ldim*Nb)     /* 8192 */
#define EE   (E*E)          /* 589824 */
#define MK   (Mrows*E)      /* 6291456 */

// ---------------- scratch (static device globals; no runtime allocation) ----
__device__ __half g_wh[4*EE];
__device__ __half g_xf[3*MK];
__device__ __half g_of[MK];
__device__ __half g_qf[BH*Ldim*HD];
__device__ __half g_kh[BH*Ldim*HD];
__device__ __half g_vf[BH*Ldim*HD];     // V in [bh][s][64] fp16 (gemm epilogue)

// ============================ helpers ========================================
__device__ __forceinline__ uint32_t smem_u32(const void* p) {
    uint32_t a;
    asm("{ .reg .u64 t; cvta.to.shared.u64 t, %1; cvt.u32.u64 %0, t; }"
        : "=r"(a) : "l"(p));
    return a;
}
__device__ __forceinline__ float ex2f(float x) {
    float y; asm("ex2.approx.f32 %0, %1;" : "=f"(y) : "f"(x)); return y;
}
#define STS128(addr, r0, r1, r2, r3) \
    asm volatile("st.shared.v4.b32 [%0], {%1, %2, %3, %4};" \
                 :: "r"(addr), "r"(r0), "r"(r1), "r"(r2), "r"(r3) : "memory")

__device__ __forceinline__ void cpa16(uint32_t dst, const void* src) {
    asm volatile("cp.async.cg.shared.global [%0], [%1], 16;"
                 :: "r"(dst), "l"(src) : "memory");
}
#define CP_COMMIT() asm volatile("cp.async.commit_group;" ::: "memory")
#define CP_WAIT0()  asm volatile("cp.async.wait_group 0;" ::: "memory")

__device__ __forceinline__ void ldm_x4(uint32_t* r, uint32_t addr) {
    asm volatile("ldmatrix.sync.aligned.m8n8.x4.shared.b16 {%0,%1,%2,%3}, [%4];"
                 : "=r"(r[0]), "=r"(r[1]), "=r"(r[2]), "=r"(r[3]) : "r"(addr));
}
__device__ __forceinline__ void ldm_x4t(uint32_t* r, uint32_t addr) {
    asm volatile("ldmatrix.sync.aligned.m8n8.x4.trans.shared.b16 {%0,%1,%2,%3}, [%4];"
                 : "=r"(r[0]), "=r"(r[1]), "=r"(r[2]), "=r"(r[3]) : "r"(addr));
}
__device__ __forceinline__ void ldm_x2(uint32_t* r, uint32_t addr) {
    asm volatile("ldmatrix.sync.aligned.m8n8.x2.shared.b16 {%0,%1}, [%2];"
                 : "=r"(r[0]), "=r"(r[1]) : "r"(addr));
}
__device__ __forceinline__ void mma16816(float* c, const uint32_t* a,
                                         const uint32_t* b) {
    asm volatile(
        "mma.sync.aligned.m16n8k16.row.col.f32.f16.f16.f32 "
        "{%0,%1,%2,%3}, {%4,%5,%6,%7}, {%8,%9}, {%0,%1,%2,%3};"
        : "+f"(c[0]), "+f"(c[1]), "+f"(c[2]), "+f"(c[3])
        : "r"(a[0]), "r"(a[1]), "r"(a[2]), "r"(a[3]), "r"(b[0]), "r"(b[1]));
}
__device__ __forceinline__ uint32_t pack2h(float a, float b) {
    __half2 h = __floats2half2_rn(a, b);
    return *reinterpret_cast<uint32_t*>(&h);
}

// ---------------- combined: W_eff fp16 pack + x fp16 pack --------------------
#define WEFF_BLOCKS 4608            /* 4 * EE/2 / 256 */
#define XSPL_BLOCKS 18432           /* 3 * MK/4 / 256 */

__global__ void __launch_bounds__(256) weff_split_kernel(
    const float* __restrict__ inW,  const float* __restrict__ outW,
    const float* __restrict__ qd, const float* __restrict__ qu,
    const float* __restrict__ kd, const float* __restrict__ ku,
    const float* __restrict__ vd, const float* __restrict__ vu,
    const float* __restrict__ od, const float* __restrict__ ou,
    const float* __restrict__ query, const float* __restrict__ key,
    const float* __restrict__ value)
{
    int bx = blockIdx.x;
    if (bx < WEFF_BLOCKS) {
        int z = bx / (WEFF_BLOCKS / 4);
        int pidx = (bx % (WEFF_BLOCKS / 4)) * 256 + threadIdx.x;
        int e = (pidx * 2) / E;
        int k = (pidx * 2) % E;
        const float* W  = (z < 3) ? (inW + z * EE) : outW;
        const float* dn = (z == 0) ? qd : (z == 1) ? kd : (z == 2) ? vd : od;
        const float* up = (z == 0) ? qu : (z == 1) ? ku : (z == 2) ? vu : ou;
        float s0 = 0.f, s1 = 0.f;
#pragma unroll
        for (int r = 0; r < 16; r++) {
            float u = up[e * 16 + r];
            s0 += u * dn[r * E + k];
            s1 += u * dn[r * E + k + 1];
        }
        float v0 = W[e * E + k] + s0;
        float v1 = W[e * E + k + 1] + s1;
        ((uint32_t*)g_wh)[(size_t)z * (EE / 2) + pidx] = pack2h(v0, v1);
    } else {
        int i = bx - WEFF_BLOCKS;
        int z = i / (XSPL_BLOCKS / 3);
        size_t idx = (size_t)(i % (XSPL_BLOCKS / 3)) * 256 + threadIdx.x;
        const float4* src = (const float4*)((z == 0) ? query : (z == 1) ? key : value);
        float4 v = src[idx];
        ((uint2*)g_xf)[(size_t)z * (MK / 4) + idx] =
            make_uint2(pack2h(v.x, v.y), pack2h(v.z, v.w));
    }
}

// ================= fp16 single-pass MMA GEMM (R14 shape, 1 sync/iter) ========
#define SKG 80                 /* smem row stride bytes (32 fp16 + pad) */
#define GA_F 0
#define GB_H 10240
#define GSTG 20480
#define G_SMEM (2*GSTG)        /* 40960 */
#define GKT (E/32)             /* 24 k-stages */

__device__ __forceinline__ void g_prefetch(
    uint32_t buf, const __half* axf, const __half* bwh,
    int m0, int e0, int k0, int tid)
{
    int row = tid >> 1, part = tid & 1;
    uint32_t ro = (uint32_t)row * SKG + (uint32_t)part * 32;
    const __half* af = axf + (size_t)(m0 + row) * E + k0 + part * 16;
    const __half* bh = bwh + (size_t)(e0 + row) * E + k0 + part * 16;
    cpa16(buf + GA_F + ro,      af); cpa16(buf + GA_F + ro + 16, af + 8);
    cpa16(buf + GB_H + ro,      bh); cpa16(buf + GB_H + ro + 16, bh + 8);
}

__global__ void __launch_bounds__(256, 2) gemm_mma(
    const __half* __restrict__ xf, const __half* __restrict__ wh,
    const float* __restrict__ bias_base,
    float* __restrict__ yout, int mode)
{
    extern __shared__ __align__(128) char smem[];
    uint32_t sb = smem_u32(smem);
    int z = blockIdx.z;
    const __half* axf = xf + (size_t)z * MK;
    const __half* bwh = wh + (size_t)z * EE;
    const float* bias = bias_base + z * E;
    int m0 = blockIdx.y * 128, e0 = blockIdx.x * 128;
    int tid = threadIdx.x, wid = tid >> 5, lane = tid & 31;
    int wm = wid & 1, wn = wid >> 1;

    uint32_t arow = (uint32_t)(wm * 64 + (lane & 15)) * SKG + (uint32_t)(lane >> 4) * 16;
    uint32_t brow = (uint32_t)(wn * 32 + (lane >> 4) * 8 + (lane & 7)) * SKG
                  + (uint32_t)((lane >> 3) & 1) * 16;

    float acc[4][4][4];
#pragma unroll
    for (int a = 0; a < 4; a++)
#pragma unroll
        for (int b = 0; b < 4; b++)
#pragma unroll
            for (int c = 0; c < 4; c++) acc[a][b][c] = 0.f;

    g_prefetch(sb, axf, bwh, m0, e0, 0, tid);
    CP_COMMIT();

    for (int kt = 0; kt < GKT; kt++) {
        uint32_t cb = sb + (uint32_t)(kt & 1) * GSTG;
        CP_WAIT0();
        __syncthreads();
        if (kt + 1 < GKT) {
            g_prefetch(sb + (uint32_t)((kt + 1) & 1) * GSTG,
                       axf, bwh, m0, e0, (kt + 1) * 32, tid);
            CP_COMMIT();
        }
#pragma unroll
        for (int ks = 0; ks < 2; ks++) {
            uint32_t koff = (uint32_t)ks * 32;
            uint32_t bhf[2][4];
            ldm_x4(bhf[0], cb + GB_H + brow + koff);
            ldm_x4(bhf[1], cb + GB_H + brow + 16 * SKG + koff);
#pragma unroll
            for (int mi = 0; mi < 4; mi++) {
                uint32_t af[4];
                ldm_x4(af, cb + GA_F + arow + mi * 16 * SKG + koff);
#pragma unroll
                for (int ni = 0; ni < 4; ni++)
                    mma16816(acc[mi][ni], af, bhf[ni >> 1] + (ni & 1) * 2);
            }
        }
    }

    int r = lane >> 2, cp = (lane & 3) * 2;
    if (mode == 1) {
        float qs = (z == 0) ? 0.125f * 1.4426950408889634f : 1.0f;
        __half* dst = (z == 0) ? g_qf : (z == 1) ? g_kh : g_vf;
#pragma unroll
        for (int mi = 0; mi < 4; mi++) {
#pragma unroll
            for (int ni = 0; ni < 4; ni++) {
                int col = e0 + wn * 32 + ni * 8 + cp;
                int hh = col >> 6, d = col & 63;
                float b0 = bias[col], b1 = bias[col + 1];
#pragma unroll
                for (int rr = 0; rr < 2; rr++) {
                    int row = m0 + wm * 64 + mi * 16 + r + rr * 8;
                    int l = row >> 2, nb = row & 3;
                    size_t w = ((((size_t)(nb * H + hh) * Ldim + l) * HD) + d) >> 1;
                    float a = (acc[mi][ni][2 * rr]     + b0) * qs;
                    float b = (acc[mi][ni][2 * rr + 1] + b1) * qs;
                    ((uint32_t*)dst)[w] = pack2h(a, b);
                }
            }
        }
    } else {
#pragma unroll
        for (int mi = 0; mi < 4; mi++) {
            int row0 = m0 + wm * 64 + mi * 16 + r;
#pragma unroll
            for (int ni = 0; ni < 4; ni++) {
                int col = e0 + wn * 32 + ni * 8 + cp;
                float b0 = bias[col], b1 = bias[col + 1];
                float2 v0 = make_float2(acc[mi][ni][0] + b0, acc[mi][ni][1] + b1);
                float2 v1 = make_float2(acc[mi][ni][2] + b0, acc[mi][ni][3] + b1);
                *(float2*)(yout + (size_t)row0 * E + col) = v0;
                *(float2*)(yout + (size_t)(row0 + 8) * E + col) = v1;
            }
        }
    }
}

// ================= warp-MMA flash attention ==================================
// K and V both in [bh][s][64] fp16; V consumed via ldmatrix.trans (no global
// transpose). Constant ones-block fragment provides l.
#define SKB 144
#define STAGE_B 18432          /* KH 9216 + VH 9216 */
#define KH_O 0
#define VH_O 9216
#define VCONST (2*STAGE_B)     /* 8 x 144 const rows */
#define S_TOTAL3 (2*STAGE_B + 8*SKB)   /* 38016 */
#define NT (Ldim / 64)

__device__ __forceinline__ void kv_prefetch(uint32_t buf, int bh, int s0, int tid)
{
    int m = tid >> 1;
    int hf = tid & 1;
    uint32_t ro = (uint32_t)m * SKB + (uint32_t)hf * 64;
    const __half* kh = g_kh + ((size_t)bh * Ldim + s0 + m) * HD + hf * 32;
    const __half* vh = g_vf + ((size_t)bh * Ldim + s0 + m) * HD + hf * 32;
#pragma unroll
    for (int c = 0; c < 4; c++) {
        cpa16(buf + KH_O + ro + c * 16, kh + c * 8);
        cpa16(buf + VH_O + ro + c * 16, vh + c * 8);
    }
}

__global__ void __launch_bounds__(128, 4) attn_mma3()
{
    extern __shared__ __align__(128) char smem[];
    uint32_t sb = smem_u32(smem);
    int tid = threadIdx.x;
    int wid = tid >> 5, lane = tid & 31;
    int bh = blockIdx.y;
    int nb = bh / H, h = bh % H;
    int q0 = blockIdx.x * 64;

    kv_prefetch(sb, bh, 0, tid);
    CP_COMMIT();

    // init constant rows: row 0 = 1.0h, rows 1-7 = 0 (72 chunks of 16B)
    if (tid < 72) {
        int rr = tid / 9, ch = tid % 9;
        uint32_t a = sb + VCONST + (uint32_t)rr * SKB + (uint32_t)ch * 16;
        uint32_t v = (rr == 0) ? 0x3C003C00u : 0u;
        STS128(a, v, v, v, v);
    }

    // stage Q through stage-1 KH region (transient; consumed pre-loop)
    {
        uint32_t q_s = sb + STAGE_B + KH_O;
        int m = tid >> 1;
        int u0 = (tid & 1) * 4;
        uint32_t o = (uint32_t)m * SKB + (uint32_t)u0 * 16;
        const uint4* s = (const uint4*)(g_qf + ((size_t)bh * Ldim + q0 + m) * HD) + u0;
        uint4 a = s[0], b = s[1], c = s[2], d = s[3];
        STS128(q_s + o,      a.x, a.y, a.z, a.w);
        STS128(q_s + o + 16, b.x, b.y, b.z, b.w);
        STS128(q_s + o + 32, c.x, c.y, c.z, c.w);
        STS128(q_s + o + 48, d.x, d.y, d.z, d.w);
    }
    __syncthreads();

    uint32_t qrow = (uint32_t)(16 * wid + (lane & 15)) * SKB + (uint32_t)(lane >> 4) * 16;
    uint32_t brow = (uint32_t)(((lane >> 4) * 8 + (lane & 7))) * SKB
                  + (uint32_t)((lane >> 3) & 1) * 16;
    // trans-load B address for V in [s][d] layout:
    // rows = k-group ((lane>>3)&1)*8 + (lane&7); byte offset = (lane>>4)*16 (n)
    uint32_t vrow = (uint32_t)((((lane >> 3) & 1) * 8) + (lane & 7)) * SKB
                  + (uint32_t)(lane >> 4) * 16;

    uint32_t qf[4][4];
#pragma unroll
    for (int k = 0; k < 4; k++)
        ldm_x4(qf[k], sb + STAGE_B + KH_O + qrow + k * 32);
    // constant ones-block B fragment (identical for every k-chunk)
    uint32_t ve[2];
    ldm_x2(ve, sb + VCONST + (uint32_t)(lane & 7) * SKB
               + (uint32_t)((lane >> 3) & 1) * 16);

    // Oa[0..7] = O columns; Oa[8] col 64 = l
    float Oa[9][4];
#pragma unroll
    for (int n = 0; n < 9; n++)
#pragma unroll
        for (int j = 0; j < 4; j++) Oa[n][j] = 0.f;
    float m_lo = -INFINITY, m_hi = -INFINITY;

    for (int t = 0; t < NT; t++) {
        uint32_t cb = sb + (uint32_t)(t & 1) * STAGE_B;
        CP_WAIT0();
        __syncthreads();
        if (t + 1 < NT) {
            kv_prefetch(sb + (uint32_t)((t + 1) & 1) * STAGE_B,
                        bh, (t + 1) * 64, tid);
            CP_COMMIT();
        }

        // ---- S = Q K^T -------------------------------------------------------
        float c[8][4];
#pragma unroll
        for (int n = 0; n < 8; n++)
#pragma unroll
            for (int j = 0; j < 4; j++) c[n][j] = 0.f;
#pragma unroll
        for (int np = 0; np < 4; np++) {
            uint32_t baseH = cb + KH_O + brow + np * (16 * SKB);
#pragma unroll
            for (int k = 0; k < 4; k++) {
                uint32_t bhh[4];
                ldm_x4(bhh, baseH + k * 32);
                mma16816(c[2 * np],     qf[k], bhh);
                mma16816(c[2 * np + 1], qf[k], bhh + 2);
            }
        }

        // ---- online softmax (quad-local rows) -------------------------------
        float mn_lo = m_lo, mn_hi = m_hi;
#pragma unroll
        for (int n = 0; n < 8; n++) {
            mn_lo = fmaxf(mn_lo, fmaxf(c[n][0], c[n][1]));
            mn_hi = fmaxf(mn_hi, fmaxf(c[n][2], c[n][3]));
        }
        mn_lo = fmaxf(mn_lo, __shfl_xor_sync(0xffffffffu, mn_lo, 1));
        mn_lo = fmaxf(mn_lo, __shfl_xor_sync(0xffffffffu, mn_lo, 2));
        mn_hi = fmaxf(mn_hi, __shfl_xor_sync(0xffffffffu, mn_hi, 1));
        mn_hi = fmaxf(mn_hi, __shfl_xor_sync(0xffffffffu, mn_hi, 2));
        bool upd = (mn_lo > m_lo) || (mn_hi > m_hi);
        if (__any_sync(0xffffffffu, upd)) {
            float corr_lo = ex2f(m_lo - mn_lo);
            float corr_hi = ex2f(m_hi - mn_hi);
#pragma unroll
            for (int n = 0; n < 9; n++) {
                Oa[n][0] *= corr_lo; Oa[n][1] *= corr_lo;
                Oa[n][2] *= corr_hi; Oa[n][3] *= corr_hi;
            }
        }
        m_lo = mn_lo; m_hi = mn_hi;

        uint32_t ph[4][4];
#pragma unroll
        for (int n = 0; n < 8; n++) {
            float p0 = ex2f(c[n][0] - m_lo);
            float p1 = ex2f(c[n][1] - m_lo);
            float p2 = ex2f(c[n][2] - m_hi);
            float p3 = ex2f(c[n][3] - m_hi);
            int kc = n >> 1, o = (n & 1) * 2;
            ph[kc][o]     = pack2h(p0, p1);
            ph[kc][o + 1] = pack2h(p2, p3);
        }

        // ---- O += P V (V via ldmatrix.trans from [s][d]) ; l += P 1 ----------
#pragma unroll
        for (int np = 0; np < 4; np++) {
            uint32_t baseV = cb + VH_O + vrow + np * 32;
#pragma unroll
            for (int k = 0; k < 4; k++) {
                uint32_t vhh[4];
                ldm_x4t(vhh, baseV + k * (16 * SKB));
                mma16816(Oa[2 * np],     ph[k], vhh);
                mma16816(Oa[2 * np + 1], ph[k], vhh + 2);
            }
        }
#pragma unroll
        for (int k = 0; k < 4; k++)
            mma16816(Oa[8], ph[k], ve);
    }

    // ---- epilogue: broadcast l from quad-lane 0, normalize, fp16 pack --------
    float l_lo = __shfl_sync(0xffffffffu, Oa[8][0], lane & ~3);
    float l_hi = __shfl_sync(0xffffffffu, Oa[8][2], lane & ~3);
    float inv_lo = 1.f / l_lo, inv_hi = 1.f / l_hi;

    int r = lane >> 2, cc = (lane & 3) * 2;
    size_t base_lo = ((size_t)(q0 + 16 * wid + r) * Nb + nb) * E + h * HD;
    size_t base_hi = ((size_t)(q0 + 16 * wid + r + 8) * Nb + nb) * E + h * HD;
#pragma unroll
    for (int n = 0; n < 8; n++) {
        int d = n * 8 + cc;
        ((uint32_t*)g_of)[(base_lo + d) >> 1] =
            pack2h(Oa[n][0] * inv_lo, Oa[n][1] * inv_lo);
        ((uint32_t*)g_of)[(base_hi + d) >> 1] =
            pack2h(Oa[n][2] * inv_hi, Oa[n][3] * inv_hi);
    }
}

// ---------------- launcher ---------------------------------------------------
extern "C" void kernel_launch(void* const* d_in, const int* in_sizes, int n_in,
                              void* d_out, int out_size)
{
    const float* query = (const float*)d_in[0];
    const float* key   = (const float*)d_in[1];
    const float* value = (const float*)d_in[2];
    const float* in_w  = (const float*)d_in[3];
    const float* in_b  = (const float*)d_in[4];
    const float* q_dn  = (const float*)d_in[5];
    const float* q_up  = (const float*)d_in[6];
    const float* k_dn  = (const float*)d_in[7];
    const float* k_up  = (const float*)d_in[8];
    const float* v_dn  = (const float*)d_in[9];
    const float* v_up  = (const float*)d_in[10];
    const float* out_w = (const float*)d_in[11];
    const float* out_b = (const float*)d_in[12];
    const float* o_dn  = (const float*)d_in[13];
    const float* o_up  = (const float*)d_in[14];

    __half *p_wh, *p_xf, *p_of;
    cudaGetSymbolAddress((void**)&p_wh, g_wh);
    cudaGetSymbolAddress((void**)&p_xf, g_xf);
    cudaGetSymbolAddress((void**)&p_of, g_of);

    cudaFuncSetAttribute(attn_mma3,
                         cudaFuncAttributeMaxDynamicSharedMemorySize, S_TOTAL3);
    cudaFuncSetAttribute(gemm_mma,
                         cudaFuncAttributeMaxDynamicSharedMemorySize, G_SMEM);

    // 1) W_eff -> fp16 + input fp16 pack
    weff_split_kernel<<<WEFF_BLOCKS + XSPL_BLOCKS, 256>>>(
        in_w, out_w, q_dn, q_up, k_dn, k_up, v_dn, v_up, o_dn, o_up,
        query, key, value);
    // 2) QKV projections; q/k/v all written in attention fp16 layout
    gemm_mma<<<dim3(E / 128, Mrows / 128, 3), 256, G_SMEM>>>(
        p_xf, p_wh, in_b, nullptr, /*mode=*/1);
    // 3) warp-MMA flash attention (V transposed in-register via ldmatrix.trans)
    attn_mma3<<<dim3(Ldim / 64, BH), 128, S_TOTAL3>>>();
    // 4) output projection -> d_out (fp32)
    gemm_mma<<<dim3(E / 128, Mrows / 128, 1), 256, G_SMEM>>>(
        p_of, p_wh + 3 * (size_t)EE, out_b, (float*)d_out, /*mode=*/0);
}